// round 1
// baseline (speedup 1.0000x reference)
#include <cuda_runtime.h>
#include <cuda_bf16.h>

// Problem dims (fixed by reference): text [A,D], video [B,V,D], out [A,B,D]
#define A_DIM 512
#define B_DIM 512
#define V_DIM 32
#define D_DIM 512
#define TEMP_INV 0.2f   // 1/5.0

#define TA 32            // a-tile per block (== warp size: lane owns a)
#define THREADS 512      // 16 warps
#define NWARP 16
#define TEXT_PAD 516     // 512 + 4 pad floats -> conflict-free strided LDS.128

// smem layout in floats:
//   video  [V][D]            : offset 0      (16384)
//   text   [TA][TEXT_PAD]    : offset 16384  (16512)  -- reused for phase-1 partials [16][32][32]
//   scores [TA][33]          : offset 32896  (1056)
//   wts    [V][33] (w[v][a]) : offset 33952  (1056)
#define SM_VID  0
#define SM_TXT  16384
#define SM_SC   32896
#define SM_W    33952
#define SM_FLOATS 35008
#define SMEM_BYTES (SM_FLOATS * 4)

__device__ __forceinline__ unsigned long long fma2(unsigned long long a,
                                                   unsigned long long b,
                                                   unsigned long long c) {
    unsigned long long d;
    asm("fma.rn.f32x2 %0, %1, %2, %3;" : "=l"(d) : "l"(a), "l"(b), "l"(c));
    return d;
}
__device__ __forceinline__ unsigned long long pack2(float x, float y) {
    unsigned long long r;
    asm("mov.b64 %0, {%1, %2};" : "=l"(r) : "f"(x), "f"(y));
    return r;
}
__device__ __forceinline__ float2 unpack2(unsigned long long r) {
    float2 f;
    asm("mov.b64 {%0, %1}, %2;" : "=f"(f.x), "=f"(f.y) : "l"(r));
    return f;
}

__global__ __launch_bounds__(THREADS, 1)
void abspool_kernel(const float* __restrict__ text,
                    const float* __restrict__ video,
                    float* __restrict__ out) {
    extern __shared__ float sm[];
    const int tid  = threadIdx.x;
    const int lane = tid & 31;
    const int warp = tid >> 5;
    const int b    = blockIdx.y;
    const int a0   = blockIdx.x * TA;

    // ---------- stage inputs ----------
    {
        const float4* gv = reinterpret_cast<const float4*>(video + (size_t)b * V_DIM * D_DIM);
        float4* sv = reinterpret_cast<float4*>(sm + SM_VID);
        #pragma unroll
        for (int i = 0; i < (V_DIM * D_DIM / 4) / THREADS; i++)
            sv[tid + i * THREADS] = gv[tid + i * THREADS];

        const float4* gt = reinterpret_cast<const float4*>(text + (size_t)a0 * D_DIM);
        #pragma unroll
        for (int i = 0; i < (TA * D_DIM / 4) / THREADS; i++) {
            int idx = tid + i * THREADS;           // float4 index in [0, 4096)
            int row = idx >> 7;                    // /128
            int c4  = idx & 127;
            float4 v = gt[idx];
            *reinterpret_cast<float4*>(sm + SM_TXT + row * TEXT_PAD + c4 * 4) = v;
        }
    }
    __syncthreads();

    // ---------- phase 1: partial scores s[a][v] over this warp's d-slice ----------
    // warp owns d in [warp*32, warp*32+32); lane owns a = a0 + lane.
    unsigned long long acc[V_DIM];
    #pragma unroll
    for (int v = 0; v < V_DIM; v++) acc[v] = 0ULL;

    {
        const float4* trow = reinterpret_cast<const float4*>(sm + SM_TXT + lane * TEXT_PAD);
        const float4* vid4 = reinterpret_cast<const float4*>(sm + SM_VID);
        #pragma unroll
        for (int dg = 0; dg < 8; dg++) {
            int d4 = warp * 8 + dg;
            float4 t = trow[d4];
            unsigned long long tlo = pack2(t.x, t.y);
            unsigned long long thi = pack2(t.z, t.w);
            #pragma unroll
            for (int v = 0; v < V_DIM; v++) {
                float4 vv = vid4[v * (D_DIM / 4) + d4];   // broadcast across warp
                acc[v] = fma2(tlo, pack2(vv.x, vv.y), acc[v]);
                acc[v] = fma2(thi, pack2(vv.z, vv.w), acc[v]);
            }
        }
    }
    __syncthreads();   // text region now dead -> reuse for partials

    // write partials: part[warp][v][a]
    {
        float* part = sm + SM_TXT;
        #pragma unroll
        for (int v = 0; v < V_DIM; v++) {
            float2 p = unpack2(acc[v]);
            part[warp * 1024 + v * 32 + lane] = p.x + p.y;
        }
    }
    __syncthreads();

    // reduce 16 partials -> scores[a][v] (padded 33)
    {
        const float* part = sm + SM_TXT;
        #pragma unroll
        for (int e = tid; e < TA * V_DIM; e += THREADS) {
            float s = 0.f;
            #pragma unroll
            for (int w = 0; w < NWARP; w++) s += part[w * 1024 + e];
            int v = e >> 5, a = e & 31;
            sm[SM_SC + a * 33 + v] = s;
        }
    }
    __syncthreads();

    // ---------- softmax over v (temp=5), store w[v][a] padded ----------
    {
        #pragma unroll
        for (int r = 0; r < 2; r++) {
            int a = warp * 2 + r;
            float l = sm[SM_SC + a * 33 + lane] * TEMP_INV;
            float m = l;
            #pragma unroll
            for (int off = 16; off > 0; off >>= 1)
                m = fmaxf(m, __shfl_xor_sync(0xFFFFFFFFu, m, off));
            float e = __expf(l - m);
            float s = e;
            #pragma unroll
            for (int off = 16; off > 0; off >>= 1)
                s += __shfl_xor_sync(0xFFFFFFFFu, s, off);
            sm[SM_W + lane * 33 + a] = e / s;   // lane == v
        }
    }
    __syncthreads();

    // ---------- phase 3: out[a][b][d] = sum_v w[v][a] * video[v][d] ----------
    // lane owns a; warp owns d-slice [warp*32, warp*32+32)
    unsigned long long w2[V_DIM];
    #pragma unroll
    for (int v = 0; v < V_DIM; v++) {
        float wv = sm[SM_W + v * 33 + lane];
        w2[v] = pack2(wv, wv);
    }

    {
        const float4* vid4 = reinterpret_cast<const float4*>(sm + SM_VID);
        float* obase = out + ((size_t)(a0 + lane) * B_DIM + b) * D_DIM + warp * 32;
        #pragma unroll
        for (int sub = 0; sub < 4; sub++) {
            int d4 = warp * 8 + sub * 2;
            unsigned long long o0 = 0, o1 = 0, o2 = 0, o3 = 0;
            #pragma unroll
            for (int v = 0; v < V_DIM; v++) {
                float4 p = vid4[v * (D_DIM / 4) + d4];
                float4 q = vid4[v * (D_DIM / 4) + d4 + 1];
                o0 = fma2(w2[v], pack2(p.x, p.y), o0);
                o1 = fma2(w2[v], pack2(p.z, p.w), o1);
                o2 = fma2(w2[v], pack2(q.x, q.y), o2);
                o3 = fma2(w2[v], pack2(q.z, q.w), o3);
            }
            float2 r0 = unpack2(o0), r1 = unpack2(o1), r2 = unpack2(o2), r3 = unpack2(o3);
            float4 f0 = make_float4(r0.x, r0.y, r1.x, r1.y);
            float4 f1 = make_float4(r2.x, r2.y, r3.x, r3.y);
            reinterpret_cast<float4*>(obase + sub * 8)[0] = f0;
            reinterpret_cast<float4*>(obase + sub * 8)[1] = f1;
        }
    }
}

extern "C" void kernel_launch(void* const* d_in, const int* in_sizes, int n_in,
                              void* d_out, int out_size) {
    const float* text  = (const float*)d_in[0];   // [512, 512]
    const float* video = (const float*)d_in[1];   // [512, 32, 512]
    float* out = (float*)d_out;                   // [512, 512, 512]

    cudaFuncSetAttribute(abspool_kernel,
                         cudaFuncAttributeMaxDynamicSharedMemorySize, SMEM_BYTES);

    dim3 grid(A_DIM / TA, B_DIM, 1);   // (16, 512)
    abspool_kernel<<<grid, THREADS, SMEM_BYTES>>>(text, video, out);
}

// round 2
// speedup vs baseline: 1.0009x; 1.0009x over previous
#include <cuda_runtime.h>
#include <cuda_bf16.h>

// Problem dims (fixed by reference): text [A,D], video [B,V,D], out [A,B,D]
#define A_DIM 512
#define B_DIM 512
#define V_DIM 32
#define D_DIM 512
#define TEMP_INV 0.2f   // 1/5.0

#define TA 32            // a-tile per block (== warp size: lane owns a)
#define THREADS 512      // 16 warps
#define NWARP 16
#define TEXT_PAD 516     // 512 + 4 pad floats -> conflict-free strided LDS.128

// smem layout in floats:
//   video  [V][D]            : offset 0      (16384)
//   text   [TA][TEXT_PAD]    : offset 16384  (16512)  -- reused for phase-1 partials [16][32][32]
//   scores [TA][33]          : offset 32896  (1056)
//   wts    [V][33] (w[v][a]) : offset 33952  (1056)
#define SM_VID  0
#define SM_TXT  16384
#define SM_SC   32896
#define SM_W    33952
#define SM_FLOATS 35008
#define SMEM_BYTES (SM_FLOATS * 4)

__device__ __forceinline__ unsigned long long fma2(unsigned long long a,
                                                   unsigned long long b,
                                                   unsigned long long c) {
    unsigned long long d;
    asm("fma.rn.f32x2 %0, %1, %2, %3;" : "=l"(d) : "l"(a), "l"(b), "l"(c));
    return d;
}
__device__ __forceinline__ unsigned long long pack2(float x, float y) {
    unsigned long long r;
    asm("mov.b64 %0, {%1, %2};" : "=l"(r) : "f"(x), "f"(y));
    return r;
}
__device__ __forceinline__ float2 unpack2(unsigned long long r) {
    float2 f;
    asm("mov.b64 {%0, %1}, %2;" : "=f"(f.x), "=f"(f.y) : "l"(r));
    return f;
}

__global__ __launch_bounds__(THREADS, 1)
void abspool_kernel(const float* __restrict__ text,
                    const float* __restrict__ video,
                    float* __restrict__ out) {
    extern __shared__ float sm[];
    const int tid  = threadIdx.x;
    const int lane = tid & 31;
    const int warp = tid >> 5;
    const int b    = blockIdx.y;
    const int a0   = blockIdx.x * TA;

    // ---------- stage inputs ----------
    {
        const float4* gv = reinterpret_cast<const float4*>(video + (size_t)b * V_DIM * D_DIM);
        float4* sv = reinterpret_cast<float4*>(sm + SM_VID);
        #pragma unroll
        for (int i = 0; i < (V_DIM * D_DIM / 4) / THREADS; i++)
            sv[tid + i * THREADS] = gv[tid + i * THREADS];

        const float4* gt = reinterpret_cast<const float4*>(text + (size_t)a0 * D_DIM);
        #pragma unroll
        for (int i = 0; i < (TA * D_DIM / 4) / THREADS; i++) {
            int idx = tid + i * THREADS;           // float4 index in [0, 4096)
            int row = idx >> 7;                    // /128
            int c4  = idx & 127;
            float4 v = gt[idx];
            *reinterpret_cast<float4*>(sm + SM_TXT + row * TEXT_PAD + c4 * 4) = v;
        }
    }
    __syncthreads();

    // ---------- phase 1: partial scores s[a][v] over this warp's d-slice ----------
    // warp owns d in [warp*32, warp*32+32); lane owns a = a0 + lane.
    unsigned long long acc[V_DIM];
    #pragma unroll
    for (int v = 0; v < V_DIM; v++) acc[v] = 0ULL;

    {
        const float4* trow = reinterpret_cast<const float4*>(sm + SM_TXT + lane * TEXT_PAD);
        const float4* vid4 = reinterpret_cast<const float4*>(sm + SM_VID);
        #pragma unroll
        for (int dg = 0; dg < 8; dg++) {
            int d4 = warp * 8 + dg;
            float4 t = trow[d4];
            unsigned long long tlo = pack2(t.x, t.y);
            unsigned long long thi = pack2(t.z, t.w);
            #pragma unroll
            for (int v = 0; v < V_DIM; v++) {
                float4 vv = vid4[v * (D_DIM / 4) + d4];   // broadcast across warp
                acc[v] = fma2(tlo, pack2(vv.x, vv.y), acc[v]);
                acc[v] = fma2(thi, pack2(vv.z, vv.w), acc[v]);
            }
        }
    }
    __syncthreads();   // text region now dead -> reuse for partials

    // write partials: part[warp][v][a]
    {
        float* part = sm + SM_TXT;
        #pragma unroll
        for (int v = 0; v < V_DIM; v++) {
            float2 p = unpack2(acc[v]);
            part[warp * 1024 + v * 32 + lane] = p.x + p.y;
        }
    }
    __syncthreads();

    // reduce 16 partials -> scores[a][v] (padded 33)
    {
        const float* part = sm + SM_TXT;
        #pragma unroll
        for (int e = tid; e < TA * V_DIM; e += THREADS) {
            float s = 0.f;
            #pragma unroll
            for (int w = 0; w < NWARP; w++) s += part[w * 1024 + e];
            int v = e >> 5, a = e & 31;
            sm[SM_SC + a * 33 + v] = s;
        }
    }
    __syncthreads();

    // ---------- softmax over v (temp=5), store w[v][a] padded ----------
    {
        #pragma unroll
        for (int r = 0; r < 2; r++) {
            int a = warp * 2 + r;
            float l = sm[SM_SC + a * 33 + lane] * TEMP_INV;
            float m = l;
            #pragma unroll
            for (int off = 16; off > 0; off >>= 1)
                m = fmaxf(m, __shfl_xor_sync(0xFFFFFFFFu, m, off));
            float e = __expf(l - m);
            float s = e;
            #pragma unroll
            for (int off = 16; off > 0; off >>= 1)
                s += __shfl_xor_sync(0xFFFFFFFFu, s, off);
            sm[SM_W + lane * 33 + a] = e / s;   // lane == v
        }
    }
    __syncthreads();

    // ---------- phase 3: out[a][b][d] = sum_v w[v][a] * video[v][d] ----------
    // lane owns a; warp owns d-slice [warp*32, warp*32+32)
    unsigned long long w2[V_DIM];
    #pragma unroll
    for (int v = 0; v < V_DIM; v++) {
        float wv = sm[SM_W + v * 33 + lane];
        w2[v] = pack2(wv, wv);
    }

    {
        const float4* vid4 = reinterpret_cast<const float4*>(sm + SM_VID);
        float* obase = out + ((size_t)(a0 + lane) * B_DIM + b) * D_DIM + warp * 32;
        #pragma unroll
        for (int sub = 0; sub < 4; sub++) {
            int d4 = warp * 8 + sub * 2;
            unsigned long long o0 = 0, o1 = 0, o2 = 0, o3 = 0;
            #pragma unroll
            for (int v = 0; v < V_DIM; v++) {
                float4 p = vid4[v * (D_DIM / 4) + d4];
                float4 q = vid4[v * (D_DIM / 4) + d4 + 1];
                o0 = fma2(w2[v], pack2(p.x, p.y), o0);
                o1 = fma2(w2[v], pack2(p.z, p.w), o1);
                o2 = fma2(w2[v], pack2(q.x, q.y), o2);
                o3 = fma2(w2[v], pack2(q.z, q.w), o3);
            }
            float2 r0 = unpack2(o0), r1 = unpack2(o1), r2 = unpack2(o2), r3 = unpack2(o3);
            float4 f0 = make_float4(r0.x, r0.y, r1.x, r1.y);
            float4 f1 = make_float4(r2.x, r2.y, r3.x, r3.y);
            reinterpret_cast<float4*>(obase + sub * 8)[0] = f0;
            reinterpret_cast<float4*>(obase + sub * 8)[1] = f1;
        }
    }
}

extern "C" void kernel_launch(void* const* d_in, const int* in_sizes, int n_in,
                              void* d_out, int out_size) {
    const float* text  = (const float*)d_in[0];   // [512, 512]
    const float* video = (const float*)d_in[1];   // [512, 32, 512]
    float* out = (float*)d_out;                   // [512, 512, 512]

    cudaFuncSetAttribute(abspool_kernel,
                         cudaFuncAttributeMaxDynamicSharedMemorySize, SMEM_BYTES);

    dim3 grid(A_DIM / TA, B_DIM, 1);   // (16, 512)
    abspool_kernel<<<grid, THREADS, SMEM_BYTES>>>(text, video, out);
}

// round 4
// speedup vs baseline: 1.3017x; 1.3006x over previous
#include <cuda_runtime.h>
#include <cuda_bf16.h>
#include <cstdint>

#define A_DIM 512
#define B_DIM 512
#define V_DIM 32
#define D_DIM 512
#define TEMP_INV 0.2f
#define THREADS 256

// bf16 hi/lo splits (allocation-free scratch)
__device__ __align__(256) __nv_bfloat16 g_TH[A_DIM * D_DIM];
__device__ __align__(256) __nv_bfloat16 g_TL[A_DIM * D_DIM];
__device__ __align__(256) __nv_bfloat16 g_VH[(size_t)B_DIM * V_DIM * D_DIM];   // [b][v][d]
__device__ __align__(256) __nv_bfloat16 g_VL[(size_t)B_DIM * V_DIM * D_DIM];
__device__ __align__(256) __nv_bfloat16 g_VtH[(size_t)B_DIM * D_DIM * V_DIM]; // [b][d][v]
__device__ __align__(256) __nv_bfloat16 g_VtL[(size_t)B_DIM * D_DIM * V_DIM];

__device__ __forceinline__ uint32_t pack_bf(float x0, float x1) {
    __nv_bfloat16 h0 = __float2bfloat16(x0), h1 = __float2bfloat16(x1);
    return (uint32_t)__bfloat16_as_ushort(h0) | ((uint32_t)__bfloat16_as_ushort(h1) << 16);
}

__device__ __forceinline__ void mma_bf16(float& d0, float& d1, float& d2, float& d3,
                                         uint32_t a0, uint32_t a1, uint32_t a2, uint32_t a3,
                                         uint32_t b0, uint32_t b1) {
    asm volatile("mma.sync.aligned.m16n8k16.row.col.f32.bf16.bf16.f32 "
                 "{%0,%1,%2,%3}, {%4,%5,%6,%7}, {%8,%9}, {%0,%1,%2,%3};"
                 : "+f"(d0), "+f"(d1), "+f"(d2), "+f"(d3)
                 : "r"(a0), "r"(a1), "r"(a2), "r"(a3), "r"(b0), "r"(b1));
}

__device__ __forceinline__ uint32_t smem_u32(const void* p) {
    uint32_t a;
    asm("{ .reg .u64 t; cvta.to.shared.u64 t, %1; cvt.u32.u64 %0, t; }" : "=r"(a) : "l"(p));
    return a;
}
__device__ __forceinline__ void cpa16(uint32_t dst, const void* src) {
    asm volatile("cp.async.cg.shared.global [%0], [%1], 16;" :: "r"(dst), "l"(src));
}

// ---------------- prep kernels ----------------
__global__ void prep_text(const float* __restrict__ t) {
    int i = blockIdx.x * 256 + threadIdx.x;           // pair index
    float x0 = t[2 * i], x1 = t[2 * i + 1];
    __nv_bfloat16 h0 = __float2bfloat16(x0), h1 = __float2bfloat16(x1);
    ((uint32_t*)g_TH)[i] = (uint32_t)__bfloat16_as_ushort(h0) | ((uint32_t)__bfloat16_as_ushort(h1) << 16);
    ((uint32_t*)g_TL)[i] = pack_bf(x0 - __bfloat162float(h0), x1 - __bfloat162float(h1));
}

__global__ void prep_video(const float* __restrict__ vid) {
    extern __shared__ float sv[];
    const int b = blockIdx.x, tid = threadIdx.x;
    const float4* g4 = reinterpret_cast<const float4*>(vid + (size_t)b * V_DIM * D_DIM);
    float4* s4 = reinterpret_cast<float4*>(sv);
    for (int i = tid; i < V_DIM * D_DIM / 4; i += 256) s4[i] = g4[i];
    __syncthreads();
    // K-major hi/lo (pairs along d)
    for (int i = tid; i < 8192; i += 256) {
        float x0 = sv[2 * i], x1 = sv[2 * i + 1];
        __nv_bfloat16 h0 = __float2bfloat16(x0), h1 = __float2bfloat16(x1);
        ((uint32_t*)g_VH)[(size_t)b * 8192 + i] =
            (uint32_t)__bfloat16_as_ushort(h0) | ((uint32_t)__bfloat16_as_ushort(h1) << 16);
        ((uint32_t*)g_VL)[(size_t)b * 8192 + i] =
            pack_bf(x0 - __bfloat162float(h0), x1 - __bfloat162float(h1));
    }
    // transposed [d][32v] hi/lo (pairs along v); row = 16 u32 words
    for (int i = tid; i < 512 * 16; i += 256) {
        int d = i >> 4, w = i & 15;
        float x0 = sv[(2 * w) * D_DIM + d], x1 = sv[(2 * w + 1) * D_DIM + d];
        __nv_bfloat16 h0 = __float2bfloat16(x0), h1 = __float2bfloat16(x1);
        size_t idx = ((size_t)b * 512 + d) * 16 + w;
        ((uint32_t*)g_VtH)[idx] = (uint32_t)__bfloat16_as_ushort(h0) | ((uint32_t)__bfloat16_as_ushort(h1) << 16);
        ((uint32_t*)g_VtL)[idx] = pack_bf(x0 - __bfloat162float(h0), x1 - __bfloat162float(h1));
    }
}

// ---------------- main ----------------
// smem: V staged hi/lo, row stride 1040B (conflict-free): 2 * 32 * 1040 = 66560 B
#define VROW_W 260          // row stride in u32 words (1040 B)
#define VSPLIT_W 8320       // split stride in words (33280 B)
#define SMEM_REQ 66560

__global__ __launch_bounds__(THREADS)
void abspool_main(float* __restrict__ out) {
    extern __shared__ uint32_t smv[];
    const int tid = threadIdx.x;
    const int wid = tid >> 5, lane = tid & 31;
    const int g = lane >> 2, tg = lane & 3;           // groupID / threadInGroup
    const int a0 = blockIdx.x * 128, b = blockIdx.y;
    const int arow = a0 + wid * 16 + g;

    // ---- stage V (both splits) into smem via cp.async
    {
        uint32_t sb = smem_u32(smv);
        for (int i = tid; i < 4096; i += THREADS) {
            int s = i >> 11, v = (i >> 6) & 31, seg = i & 63;
            cpa16(sb + s * 33280 + v * 1040 + seg * 16,
                  (s ? g_VL : g_VH) + (size_t)b * 16384 + v * 512 + seg * 8);
        }
        asm volatile("cp.async.commit_group;" ::: "memory");
        asm volatile("cp.async.wait_group 0;" ::: "memory");
        __syncthreads();
    }

    // ---- GEMM1: S[16a, 32v] per warp, bf16x3 ----
    float acc[4][4];
    #pragma unroll
    for (int nt = 0; nt < 4; nt++)
        #pragma unroll
        for (int j = 0; j < 4; j++) acc[nt][j] = 0.f;

    const uint32_t* tHp = (const uint32_t*)g_TH + (size_t)arow * 256 + tg;
    const uint32_t* tLp = (const uint32_t*)g_TL + (size_t)arow * 256 + tg;
    const int vbase = g * VROW_W + tg;                // word index of b0 for this thread

    #pragma unroll 4
    for (int kc = 0; kc < 32; kc++) {
        uint32_t aH0 = tHp[kc * 8],     aH1 = tHp[kc * 8 + 2048];
        uint32_t aH2 = tHp[kc * 8 + 4], aH3 = tHp[kc * 8 + 2048 + 4];
        uint32_t aL0 = tLp[kc * 8],     aL1 = tLp[kc * 8 + 2048];
        uint32_t aL2 = tLp[kc * 8 + 4], aL3 = tLp[kc * 8 + 2048 + 4];
        uint32_t bH[4][2], bL[4][2];
        #pragma unroll
        for (int nt = 0; nt < 4; nt++) {
            int w0 = vbase + nt * 8 * VROW_W + kc * 8;
            bH[nt][0] = smv[w0];            bH[nt][1] = smv[w0 + 4];
            bL[nt][0] = smv[w0 + VSPLIT_W]; bL[nt][1] = smv[w0 + VSPLIT_W + 4];
        }
        #pragma unroll
        for (int nt = 0; nt < 4; nt++)
            mma_bf16(acc[nt][0], acc[nt][1], acc[nt][2], acc[nt][3],
                     aH0, aH1, aH2, aH3, bH[nt][0], bH[nt][1]);
        #pragma unroll
        for (int nt = 0; nt < 4; nt++)
            mma_bf16(acc[nt][0], acc[nt][1], acc[nt][2], acc[nt][3],
                     aH0, aH1, aH2, aH3, bL[nt][0], bL[nt][1]);
        #pragma unroll
        for (int nt = 0; nt < 4; nt++)
            mma_bf16(acc[nt][0], acc[nt][1], acc[nt][2], acc[nt][3],
                     aL0, aL1, aL2, aL3, bH[nt][0], bH[nt][1]);
    }

    // ---- softmax in registers (two rows per thread: g and g+8) ----
    // row g: acc[nt][0..1], row g+8: acc[nt][2..3]; full row spread over quad (tg)
    float m0 = -1e30f, m1 = -1e30f;
    #pragma unroll
    for (int nt = 0; nt < 4; nt++) {
        m0 = fmaxf(m0, fmaxf(acc[nt][0], acc[nt][1]));
        m1 = fmaxf(m1, fmaxf(acc[nt][2], acc[nt][3]));
    }
    m0 = fmaxf(m0, __shfl_xor_sync(0xFFFFFFFFu, m0, 1));
    m0 = fmaxf(m0, __shfl_xor_sync(0xFFFFFFFFu, m0, 2));
    m1 = fmaxf(m1, __shfl_xor_sync(0xFFFFFFFFu, m1, 1));
    m1 = fmaxf(m1, __shfl_xor_sync(0xFFFFFFFFu, m1, 2));
    float sum0 = 0.f, sum1 = 0.f;
    float w[4][4];
    #pragma unroll
    for (int nt = 0; nt < 4; nt++) {
        w[nt][0] = __expf((acc[nt][0] - m0) * TEMP_INV);
        w[nt][1] = __expf((acc[nt][1] - m0) * TEMP_INV);
        w[nt][2] = __expf((acc[nt][2] - m1) * TEMP_INV);
        w[nt][3] = __expf((acc[nt][3] - m1) * TEMP_INV);
        sum0 += w[nt][0] + w[nt][1];
        sum1 += w[nt][2] + w[nt][3];
    }
    sum0 += __shfl_xor_sync(0xFFFFFFFFu, sum0, 1);
    sum0 += __shfl_xor_sync(0xFFFFFFFFu, sum0, 2);
    sum1 += __shfl_xor_sync(0xFFFFFFFFu, sum1, 1);
    sum1 += __shfl_xor_sync(0xFFFFFFFFu, sum1, 2);
    float inv0 = 1.f / sum0, inv1 = 1.f / sum1;
    #pragma unroll
    for (int nt = 0; nt < 4; nt++) {
        w[nt][0] *= inv0; w[nt][1] *= inv0;
        w[nt][2] *= inv1; w[nt][3] *= inv1;
    }

    // D-frag -> A-frag conversion (hi/lo), 2 k-chunks of 16 v
    uint32_t aWH[2][4], aWL[2][4];
    #pragma unroll
    for (int c = 0; c < 2; c++) {
        #pragma unroll
        for (int h = 0; h < 2; h++) {        // h=0: cols 0-7 (ntile 2c), h=1: cols 8-15 (2c+1)
            int nt = 2 * c + h;
            float x0 = w[nt][0], x1 = w[nt][1], x2 = w[nt][2], x3 = w[nt][3];
            __nv_bfloat16 h0 = __float2bfloat16(x0), h1 = __float2bfloat16(x1);
            __nv_bfloat16 h2 = __float2bfloat16(x2), h3 = __float2bfloat16(x3);
            aWH[c][2 * h + 0] = (uint32_t)__bfloat16_as_ushort(h0) | ((uint32_t)__bfloat16_as_ushort(h1) << 16);
            aWH[c][2 * h + 1] = (uint32_t)__bfloat16_as_ushort(h2) | ((uint32_t)__bfloat16_as_ushort(h3) << 16);
            aWL[c][2 * h + 0] = pack_bf(x0 - __bfloat162float(h0), x1 - __bfloat162float(h1));
            aWL[c][2 * h + 1] = pack_bf(x2 - __bfloat162float(h2), x3 - __bfloat162float(h3));
        }
    }

    // ---- GEMM2: out[16a, 512d] = W[16,32] * Vt[32,512], bf16x3 ----
    const uint32_t* vHp = (const uint32_t*)g_VtH + ((size_t)b * 512 + g) * 16 + tg;
    const uint32_t* vLp = (const uint32_t*)g_VtL + ((size_t)b * 512 + g) * 16 + tg;
    float* o0 = out + ((size_t)arow * 512 + b) * 512;
    float* o1 = o0 + (size_t)8 * 512 * 512;

    #pragma unroll 2
    for (int nt = 0; nt < 64; nt++) {
        const uint32_t* pH = vHp + nt * 128;
        const uint32_t* pL = vLp + nt * 128;
        uint32_t bh00 = pH[0], bh01 = pH[4], bh10 = pH[8], bh11 = pH[12];
        uint32_t bl00 = pL[0], bl01 = pL[4], bl10 = pL[8], bl11 = pL[12];
        float d0 = 0.f, d1 = 0.f, d2 = 0.f, d3 = 0.f;
        mma_bf16(d0, d1, d2, d3, aWH[0][0], aWH[0][1], aWH[0][2], aWH[0][3], bh00, bh01);
        mma_bf16(d0, d1, d2, d3, aWH[1][0], aWH[1][1], aWH[1][2], aWH[1][3], bh10, bh11);
        mma_bf16(d0, d1, d2, d3, aWH[0][0], aWH[0][1], aWH[0][2], aWH[0][3], bl00, bl01);
        mma_bf16(d0, d1, d2, d3, aWH[1][0], aWH[1][1], aWH[1][2], aWH[1][3], bl10, bl11);
        mma_bf16(d0, d1, d2, d3, aWL[0][0], aWL[0][1], aWL[0][2], aWL[0][3], bh00, bh01);
        mma_bf16(d0, d1, d2, d3, aWL[1][0], aWL[1][1], aWL[1][2], aWL[1][3], bh10, bh11);
        int dcol = nt * 8 + tg * 2;
        *reinterpret_cast<float2*>(o0 + dcol) = make_float2(d0, d1);
        *reinterpret_cast<float2*>(o1 + dcol) = make_float2(d2, d3);
    }
}

extern "C" void kernel_launch(void* const* d_in, const int* in_sizes, int n_in,
                              void* d_out, int out_size) {
    const float* text = (const float*)d_in[0];
    const float* video = (const float*)d_in[1];
    float* out = (float*)d_out;

    cudaFuncSetAttribute(prep_video, cudaFuncAttributeMaxDynamicSharedMemorySize, 65536);
    cudaFuncSetAttribute(abspool_main, cudaFuncAttributeMaxDynamicSharedMemorySize, SMEM_REQ);

    prep_text<<<A_DIM * D_DIM / 512, 256>>>(text);
    prep_video<<<B_DIM, 256, 65536>>>(video);
    dim3 grid(A_DIM / 128, B_DIM, 1);   // (4, 512)
    abspool_main<<<grid, THREADS, SMEM_REQ>>>(out);
}

// round 5
// speedup vs baseline: 1.9902x; 1.5288x over previous
#include <cuda_runtime.h>
#include <cuda_bf16.h>
#include <cstdint>

#define A_DIM 512
#define B_DIM 512
#define V_DIM 32
#define D_DIM 512
#define TEMP_INV 0.2f
#define THREADS 256

// fragment-packed operand buffers (allocation-free scratch)
// TF  : [tile(32)][kc(32)][split(2)][lane(32)] uint4  -> 1 MB
// V1F : [b(512)][kc(32)][nt(4)][lane(32)]     uint4  -> 32 MB  (hi+lo packed per entry)
// VF2 : [b(512)][nt(64)][split(2)][lane(32)]  uint4  -> 32 MB
__device__ __align__(256) uint4 g_TF [32 * 32 * 2 * 32];
__device__ __align__(256) uint4 g_V1F[(size_t)B_DIM * 32 * 4 * 32];
__device__ __align__(256) uint4 g_VF2[(size_t)B_DIM * 64 * 2 * 32];

__device__ __forceinline__ uint32_t pack_bf(float x0, float x1) {
    __nv_bfloat16 h0 = __float2bfloat16(x0), h1 = __float2bfloat16(x1);
    return (uint32_t)__bfloat16_as_ushort(h0) | ((uint32_t)__bfloat16_as_ushort(h1) << 16);
}
__device__ __forceinline__ uint32_t pack_res(float x0, float x1) {
    float r0 = x0 - __bfloat162float(__float2bfloat16(x0));
    float r1 = x1 - __bfloat162float(__float2bfloat16(x1));
    return pack_bf(r0, r1);
}

__device__ __forceinline__ void mma_bf16(float& d0, float& d1, float& d2, float& d3,
                                         uint32_t a0, uint32_t a1, uint32_t a2, uint32_t a3,
                                         uint32_t b0, uint32_t b1) {
    asm volatile("mma.sync.aligned.m16n8k16.row.col.f32.bf16.bf16.f32 "
                 "{%0,%1,%2,%3}, {%4,%5,%6,%7}, {%8,%9}, {%0,%1,%2,%3};"
                 : "+f"(d0), "+f"(d1), "+f"(d2), "+f"(d3)
                 : "r"(a0), "r"(a1), "r"(a2), "r"(a3), "r"(b0), "r"(b1));
}

// ---------------- prep: text A-fragments ----------------
// i = tile*2048 + kc*64 + s*32 + lane
__global__ void prep_text(const float* __restrict__ t) {
    int i = blockIdx.x * 256 + threadIdx.x;      // 0..65535
    int lane = i & 31, s = (i >> 5) & 1, kc = (i >> 6) & 31, tile = i >> 11;
    int g = lane >> 2, tg = lane & 3;
    const float* r0 = t + (size_t)(tile * 16 + g) * D_DIM;
    const float* r1 = r0 + 8 * D_DIM;
    int d0 = kc * 16 + 2 * tg, d1 = d0 + 8;
    uint4 w;
    if (s == 0) {
        w.x = pack_bf(r0[d0], r0[d0 + 1]);
        w.y = pack_bf(r1[d0], r1[d0 + 1]);
        w.z = pack_bf(r0[d1], r0[d1 + 1]);
        w.w = pack_bf(r1[d1], r1[d1 + 1]);
    } else {
        w.x = pack_res(r0[d0], r0[d0 + 1]);
        w.y = pack_res(r1[d0], r1[d0 + 1]);
        w.z = pack_res(r0[d1], r0[d1 + 1]);
        w.w = pack_res(r1[d1], r1[d1 + 1]);
    }
    g_TF[i] = w;
}

// ---------------- prep: video B-fragments (both GEMMs) ----------------
__global__ void prep_video(const float* __restrict__ vid) {
    extern __shared__ float sv[];                 // [32 v][512 d] fp32
    const int b = blockIdx.x, tid = threadIdx.x;
    const float4* g4 = reinterpret_cast<const float4*>(vid + (size_t)b * V_DIM * D_DIM);
    float4* s4 = reinterpret_cast<float4*>(sv);
    for (int i = tid; i < V_DIM * D_DIM / 4; i += 256) s4[i] = g4[i];
    __syncthreads();

    // V1F: e = kc*128 + nt*32 + lane  ; entry {bH0,bH1,bL0,bL1}
    for (int e = tid; e < 4096; e += 256) {
        int lane = e & 31, nt = (e >> 5) & 3, kc = e >> 7;
        int g = lane >> 2, tg = lane & 3;
        const float* vr = sv + (nt * 8 + g) * D_DIM;
        int d0 = kc * 16 + 2 * tg, d1 = d0 + 8;
        uint4 w;
        w.x = pack_bf (vr[d0], vr[d0 + 1]);
        w.y = pack_bf (vr[d1], vr[d1 + 1]);
        w.z = pack_res(vr[d0], vr[d0 + 1]);
        w.w = pack_res(vr[d1], vr[d1 + 1]);
        g_V1F[(size_t)b * 4096 + e] = w;
    }
    // VF2: e = nt*64 + s*32 + lane ; entry {c0b0, c0b1, c1b0, c1b1} for split s
    for (int e = tid; e < 4096; e += 256) {
        int lane = e & 31, s = (e >> 5) & 1, nt = e >> 6;
        int g = lane >> 2, tg = lane & 3;
        int d = nt * 8 + g;
        float v0a = sv[(2 * tg) * D_DIM + d],      v0b = sv[(2 * tg + 1) * D_DIM + d];
        float v1a = sv[(8 + 2 * tg) * D_DIM + d],  v1b = sv[(9 + 2 * tg) * D_DIM + d];
        float v2a = sv[(16 + 2 * tg) * D_DIM + d], v2b = sv[(17 + 2 * tg) * D_DIM + d];
        float v3a = sv[(24 + 2 * tg) * D_DIM + d], v3b = sv[(25 + 2 * tg) * D_DIM + d];
        uint4 w;
        if (s == 0) {
            w.x = pack_bf(v0a, v0b); w.y = pack_bf(v1a, v1b);
            w.z = pack_bf(v2a, v2b); w.w = pack_bf(v3a, v3b);
        } else {
            w.x = pack_res(v0a, v0b); w.y = pack_res(v1a, v1b);
            w.z = pack_res(v2a, v2b); w.w = pack_res(v3a, v3b);
        }
        g_VF2[(size_t)b * 4096 + e] = w;
    }
}

// ---------------- main: no smem, no syncs ----------------
__global__ __launch_bounds__(THREADS)
void abspool_main(float* __restrict__ out) {
    const int tid = threadIdx.x;
    const int wid = tid >> 5, lane = tid & 31;
    const int b = blockIdx.y;
    const int tile = blockIdx.x * 8 + wid;        // 16-row a-tile index
    const int arow = tile * 16 + (lane >> 2);

    const uint4* tF = g_TF  + (size_t)tile * 2048 + lane;
    const uint4* vF = g_V1F + (size_t)b * 4096 + lane;

    // ---- GEMM1: S[16a, 32v], bf16x3 ----
    float acc[4][4];
    #pragma unroll
    for (int nt = 0; nt < 4; nt++)
        #pragma unroll
        for (int j = 0; j < 4; j++) acc[nt][j] = 0.f;

    #pragma unroll 2
    for (int kc = 0; kc < 32; kc++) {
        uint4 aH = tF[kc * 64];
        uint4 aL = tF[kc * 64 + 32];
        uint4 bv[4];
        #pragma unroll
        for (int nt = 0; nt < 4; nt++) bv[nt] = vF[kc * 128 + nt * 32];
        #pragma unroll
        for (int nt = 0; nt < 4; nt++)
            mma_bf16(acc[nt][0], acc[nt][1], acc[nt][2], acc[nt][3],
                     aH.x, aH.y, aH.z, aH.w, bv[nt].x, bv[nt].y);
        #pragma unroll
        for (int nt = 0; nt < 4; nt++)
            mma_bf16(acc[nt][0], acc[nt][1], acc[nt][2], acc[nt][3],
                     aH.x, aH.y, aH.z, aH.w, bv[nt].z, bv[nt].w);
        #pragma unroll
        for (int nt = 0; nt < 4; nt++)
            mma_bf16(acc[nt][0], acc[nt][1], acc[nt][2], acc[nt][3],
                     aL.x, aL.y, aL.z, aL.w, bv[nt].x, bv[nt].y);
    }

    // ---- softmax in registers (rows g and g+8, spread over quad) ----
    float m0 = -1e30f, m1 = -1e30f;
    #pragma unroll
    for (int nt = 0; nt < 4; nt++) {
        m0 = fmaxf(m0, fmaxf(acc[nt][0], acc[nt][1]));
        m1 = fmaxf(m1, fmaxf(acc[nt][2], acc[nt][3]));
    }
    m0 = fmaxf(m0, __shfl_xor_sync(0xFFFFFFFFu, m0, 1));
    m0 = fmaxf(m0, __shfl_xor_sync(0xFFFFFFFFu, m0, 2));
    m1 = fmaxf(m1, __shfl_xor_sync(0xFFFFFFFFu, m1, 1));
    m1 = fmaxf(m1, __shfl_xor_sync(0xFFFFFFFFu, m1, 2));
    float sum0 = 0.f, sum1 = 0.f;
    float w[4][4];
    #pragma unroll
    for (int nt = 0; nt < 4; nt++) {
        w[nt][0] = __expf((acc[nt][0] - m0) * TEMP_INV);
        w[nt][1] = __expf((acc[nt][1] - m0) * TEMP_INV);
        w[nt][2] = __expf((acc[nt][2] - m1) * TEMP_INV);
        w[nt][3] = __expf((acc[nt][3] - m1) * TEMP_INV);
        sum0 += w[nt][0] + w[nt][1];
        sum1 += w[nt][2] + w[nt][3];
    }
    sum0 += __shfl_xor_sync(0xFFFFFFFFu, sum0, 1);
    sum0 += __shfl_xor_sync(0xFFFFFFFFu, sum0, 2);
    sum1 += __shfl_xor_sync(0xFFFFFFFFu, sum1, 1);
    sum1 += __shfl_xor_sync(0xFFFFFFFFu, sum1, 2);
    float inv0 = 1.f / sum0, inv1 = 1.f / sum1;
    #pragma unroll
    for (int nt = 0; nt < 4; nt++) {
        w[nt][0] *= inv0; w[nt][1] *= inv0;
        w[nt][2] *= inv1; w[nt][3] *= inv1;
    }

    // D-frag -> A-frag (hi/lo), k-chunks c of 16 v
    uint32_t aWH[2][4], aWL[2][4];
    #pragma unroll
    for (int c = 0; c < 2; c++) {
        #pragma unroll
        for (int h = 0; h < 2; h++) {
            int nt = 2 * c + h;
            float x0 = w[nt][0], x1 = w[nt][1], x2 = w[nt][2], x3 = w[nt][3];
            aWH[c][2 * h + 0] = pack_bf(x0, x1);
            aWH[c][2 * h + 1] = pack_bf(x2, x3);
            aWL[c][2 * h + 0] = pack_res(x0, x1);
            aWL[c][2 * h + 1] = pack_res(x2, x3);
        }
    }

    // ---- GEMM2: out[16a, 512d] = W[16,32] * V[32,512], bf16x3 ----
    const uint4* v2 = g_VF2 + (size_t)b * 4096 + lane;
    float* o0 = out + ((size_t)arow * B_DIM + b) * D_DIM;
    float* o1 = o0 + (size_t)8 * B_DIM * D_DIM;

    #pragma unroll 2
    for (int nt = 0; nt < 64; nt++) {
        uint4 h = v2[nt * 64];
        uint4 l = v2[nt * 64 + 32];
        float d0 = 0.f, d1 = 0.f, d2 = 0.f, d3 = 0.f;
        mma_bf16(d0, d1, d2, d3, aWH[0][0], aWH[0][1], aWH[0][2], aWH[0][3], h.x, h.y);
        mma_bf16(d0, d1, d2, d3, aWH[1][0], aWH[1][1], aWH[1][2], aWH[1][3], h.z, h.w);
        mma_bf16(d0, d1, d2, d3, aWH[0][0], aWH[0][1], aWH[0][2], aWH[0][3], l.x, l.y);
        mma_bf16(d0, d1, d2, d3, aWH[1][0], aWH[1][1], aWH[1][2], aWH[1][3], l.z, l.w);
        mma_bf16(d0, d1, d2, d3, aWL[0][0], aWL[0][1], aWL[0][2], aWL[0][3], h.x, h.y);
        mma_bf16(d0, d1, d2, d3, aWL[1][0], aWL[1][1], aWL[1][2], aWL[1][3], h.z, h.w);
        int dcol = nt * 8 + (lane & 3) * 2;
        *reinterpret_cast<float2*>(o0 + dcol) = make_float2(d0, d1);
        *reinterpret_cast<float2*>(o1 + dcol) = make_float2(d2, d3);
    }
}

extern "C" void kernel_launch(void* const* d_in, const int* in_sizes, int n_in,
                              void* d_out, int out_size) {
    const float* text = (const float*)d_in[0];
    const float* video = (const float*)d_in[1];
    float* out = (float*)d_out;

    cudaFuncSetAttribute(prep_video, cudaFuncAttributeMaxDynamicSharedMemorySize, 65536);

    prep_text<<<256, 256>>>(text);                 // 65536 entries
    prep_video<<<B_DIM, 256, 65536>>>(video);
    dim3 grid(A_DIM / 128, B_DIM, 1);              // (4, 512)
    abspool_main<<<grid, THREADS>>>(out);
}

// round 6
// speedup vs baseline: 3.1041x; 1.5597x over previous
#include <cuda_runtime.h>
#include <cuda_bf16.h>
#include <cuda_fp16.h>
#include <cstdint>

#define A_DIM 512
#define B_DIM 512
#define V_DIM 32
#define D_DIM 512
#define TEMP_INV 0.2f
#define THREADS 256

// fragment-packed operand buffers (padded for one-past prefetch reads)
// TF  : [tile(32)][kc(32)][split(2)][lane(32)] uint4  -> 1 MB   (bf16 hi/lo)
// V1F : [b(512)][kc(32)][nt(4)][lane(32)]      uint4  -> 32 MB  (bf16 hi+lo packed)
// VF2 : [b(512)][nt(64)][split(2)][lane(32)]   uint4  -> 32 MB  (fp16 hi/lo)
__device__ __align__(256) uint4 g_TF [32 * 32 * 2 * 32 + 128];
__device__ __align__(256) uint4 g_V1F[(size_t)B_DIM * 32 * 4 * 32 + 256];
__device__ __align__(256) uint4 g_VF2[(size_t)B_DIM * 64 * 2 * 32 + 256];

__device__ __forceinline__ uint32_t pack_bf(float x0, float x1) {
    __nv_bfloat16 h0 = __float2bfloat16(x0), h1 = __float2bfloat16(x1);
    return (uint32_t)__bfloat16_as_ushort(h0) | ((uint32_t)__bfloat16_as_ushort(h1) << 16);
}
__device__ __forceinline__ uint32_t pack_res(float x0, float x1) {
    float r0 = x0 - __bfloat162float(__float2bfloat16(x0));
    float r1 = x1 - __bfloat162float(__float2bfloat16(x1));
    return pack_bf(r0, r1);
}
__device__ __forceinline__ uint32_t pack_h(float x0, float x1) {
    __half2 h = __floats2half2_rn(x0, x1);
    return *reinterpret_cast<uint32_t*>(&h);
}
__device__ __forceinline__ uint32_t pack_res_h(float x0, float x1) {
    float r0 = x0 - __half2float(__float2half_rn(x0));
    float r1 = x1 - __half2float(__float2half_rn(x1));
    return pack_h(r0, r1);
}

__device__ __forceinline__ void mma_bf16(float& d0, float& d1, float& d2, float& d3,
                                         uint32_t a0, uint32_t a1, uint32_t a2, uint32_t a3,
                                         uint32_t b0, uint32_t b1) {
    asm volatile("mma.sync.aligned.m16n8k16.row.col.f32.bf16.bf16.f32 "
                 "{%0,%1,%2,%3}, {%4,%5,%6,%7}, {%8,%9}, {%0,%1,%2,%3};"
                 : "+f"(d0), "+f"(d1), "+f"(d2), "+f"(d3)
                 : "r"(a0), "r"(a1), "r"(a2), "r"(a3), "r"(b0), "r"(b1));
}
__device__ __forceinline__ void mma_f16(float& d0, float& d1, float& d2, float& d3,
                                        uint32_t a0, uint32_t a1, uint32_t a2, uint32_t a3,
                                        uint32_t b0, uint32_t b1) {
    asm volatile("mma.sync.aligned.m16n8k16.row.col.f32.f16.f16.f32 "
                 "{%0,%1,%2,%3}, {%4,%5,%6,%7}, {%8,%9}, {%0,%1,%2,%3};"
                 : "+f"(d0), "+f"(d1), "+f"(d2), "+f"(d3)
                 : "r"(a0), "r"(a1), "r"(a2), "r"(a3), "r"(b0), "r"(b1));
}

// ---------------- prep: text A-fragments (bf16 hi/lo) ----------------
__global__ void prep_text(const float* __restrict__ t) {
    int i = blockIdx.x * 256 + threadIdx.x;      // 0..65535
    int lane = i & 31, s = (i >> 5) & 1, kc = (i >> 6) & 31, tile = i >> 11;
    int g = lane >> 2, tg = lane & 3;
    const float* r0 = t + (size_t)(tile * 16 + g) * D_DIM;
    const float* r1 = r0 + 8 * D_DIM;
    int d0 = kc * 16 + 2 * tg, d1 = d0 + 8;
    uint4 w;
    if (s == 0) {
        w.x = pack_bf(r0[d0], r0[d0 + 1]);
        w.y = pack_bf(r1[d0], r1[d0 + 1]);
        w.z = pack_bf(r0[d1], r0[d1 + 1]);
        w.w = pack_bf(r1[d1], r1[d1 + 1]);
    } else {
        w.x = pack_res(r0[d0], r0[d0 + 1]);
        w.y = pack_res(r1[d0], r1[d0 + 1]);
        w.z = pack_res(r0[d1], r0[d1 + 1]);
        w.w = pack_res(r1[d1], r1[d1 + 1]);
    }
    g_TF[i] = w;
}

// ---------------- prep: video B-fragments ----------------
__global__ void prep_video(const float* __restrict__ vid) {
    extern __shared__ float sv[];                 // [32 v][512 d] fp32
    const int b = blockIdx.x, tid = threadIdx.x;
    const float4* g4 = reinterpret_cast<const float4*>(vid + (size_t)b * V_DIM * D_DIM);
    float4* s4 = reinterpret_cast<float4*>(sv);
    for (int i = tid; i < V_DIM * D_DIM / 4; i += 256) s4[i] = g4[i];
    __syncthreads();

    // V1F (GEMM1, bf16): e = kc*128 + nt*32 + lane ; entry {bH0,bH1,bL0,bL1}
    for (int e = tid; e < 4096; e += 256) {
        int lane = e & 31, nt = (e >> 5) & 3, kc = e >> 7;
        int g = lane >> 2, tg = lane & 3;
        const float* vr = sv + (nt * 8 + g) * D_DIM;
        int d0 = kc * 16 + 2 * tg, d1 = d0 + 8;
        uint4 w;
        w.x = pack_bf (vr[d0], vr[d0 + 1]);
        w.y = pack_bf (vr[d1], vr[d1 + 1]);
        w.z = pack_res(vr[d0], vr[d0 + 1]);
        w.w = pack_res(vr[d1], vr[d1 + 1]);
        g_V1F[(size_t)b * 4096 + e] = w;
    }
    // VF2 (GEMM2, fp16 hi/lo): e = nt*64 + s*32 + lane ; entry {c0b0,c0b1,c1b0,c1b1}
    for (int e = tid; e < 4096; e += 256) {
        int lane = e & 31, s = (e >> 5) & 1, nt = e >> 6;
        int g = lane >> 2, tg = lane & 3;
        int d = nt * 8 + g;
        float v0a = sv[(2 * tg) * D_DIM + d],      v0b = sv[(2 * tg + 1) * D_DIM + d];
        float v1a = sv[(8 + 2 * tg) * D_DIM + d],  v1b = sv[(9 + 2 * tg) * D_DIM + d];
        float v2a = sv[(16 + 2 * tg) * D_DIM + d], v2b = sv[(17 + 2 * tg) * D_DIM + d];
        float v3a = sv[(24 + 2 * tg) * D_DIM + d], v3b = sv[(25 + 2 * tg) * D_DIM + d];
        uint4 w;
        if (s == 0) {
            w.x = pack_h(v0a, v0b); w.y = pack_h(v1a, v1b);
            w.z = pack_h(v2a, v2b); w.w = pack_h(v3a, v3b);
        } else {
            w.x = pack_res_h(v0a, v0b); w.y = pack_res_h(v1a, v1b);
            w.z = pack_res_h(v2a, v2b); w.w = pack_res_h(v3a, v3b);
        }
        g_VF2[(size_t)b * 4096 + e] = w;
    }
}

// ---------------- main: no smem, no syncs ----------------
__global__ __launch_bounds__(THREADS, 2)
void abspool_main(float* __restrict__ out) {
    const int tid = threadIdx.x;
    const int wid = tid >> 5, lane = tid & 31;
    const int b = blockIdx.y;
    const int tile = blockIdx.x * 8 + wid;        // 16-row a-tile index
    const int arow = tile * 16 + (lane >> 2);

    const uint4* tF = g_TF  + (size_t)tile * 2048 + lane;
    const uint4* vF = g_V1F + (size_t)b * 4096 + lane;

    // ---- GEMM1: S[16a, 32v], bf16x3, register double-buffered ----
    float acc[4][4];
    #pragma unroll
    for (int nt = 0; nt < 4; nt++)
        #pragma unroll
        for (int j = 0; j < 4; j++) acc[nt][j] = 0.f;

    uint4 aH = tF[0], aL = tF[32];
    uint4 bv[4];
    #pragma unroll
    for (int nt = 0; nt < 4; nt++) bv[nt] = vF[nt * 32];

    #pragma unroll 2
    for (int kc = 0; kc < 32; kc++) {
        // prefetch next kc (padded buffers make kc==31 read safe)
        uint4 naH = tF[(kc + 1) * 64];
        uint4 naL = tF[(kc + 1) * 64 + 32];
        uint4 nbv[4];
        #pragma unroll
        for (int nt = 0; nt < 4; nt++) nbv[nt] = vF[(kc + 1) * 128 + nt * 32];

        #pragma unroll
        for (int nt = 0; nt < 4; nt++)
            mma_bf16(acc[nt][0], acc[nt][1], acc[nt][2], acc[nt][3],
                     aH.x, aH.y, aH.z, aH.w, bv[nt].x, bv[nt].y);
        #pragma unroll
        for (int nt = 0; nt < 4; nt++)
            mma_bf16(acc[nt][0], acc[nt][1], acc[nt][2], acc[nt][3],
                     aH.x, aH.y, aH.z, aH.w, bv[nt].z, bv[nt].w);
        #pragma unroll
        for (int nt = 0; nt < 4; nt++)
            mma_bf16(acc[nt][0], acc[nt][1], acc[nt][2], acc[nt][3],
                     aL.x, aL.y, aL.z, aL.w, bv[nt].x, bv[nt].y);

        aH = naH; aL = naL;
        #pragma unroll
        for (int nt = 0; nt < 4; nt++) bv[nt] = nbv[nt];
    }

    // ---- softmax in registers (rows g and g+8, spread over quad) ----
    float m0 = -1e30f, m1 = -1e30f;
    #pragma unroll
    for (int nt = 0; nt < 4; nt++) {
        m0 = fmaxf(m0, fmaxf(acc[nt][0], acc[nt][1]));
        m1 = fmaxf(m1, fmaxf(acc[nt][2], acc[nt][3]));
    }
    m0 = fmaxf(m0, __shfl_xor_sync(0xFFFFFFFFu, m0, 1));
    m0 = fmaxf(m0, __shfl_xor_sync(0xFFFFFFFFu, m0, 2));
    m1 = fmaxf(m1, __shfl_xor_sync(0xFFFFFFFFu, m1, 1));
    m1 = fmaxf(m1, __shfl_xor_sync(0xFFFFFFFFu, m1, 2));
    float sum0 = 0.f, sum1 = 0.f;
    float w[4][4];
    #pragma unroll
    for (int nt = 0; nt < 4; nt++) {
        w[nt][0] = __expf((acc[nt][0] - m0) * TEMP_INV);
        w[nt][1] = __expf((acc[nt][1] - m0) * TEMP_INV);
        w[nt][2] = __expf((acc[nt][2] - m1) * TEMP_INV);
        w[nt][3] = __expf((acc[nt][3] - m1) * TEMP_INV);
        sum0 += w[nt][0] + w[nt][1];
        sum1 += w[nt][2] + w[nt][3];
    }
    sum0 += __shfl_xor_sync(0xFFFFFFFFu, sum0, 1);
    sum0 += __shfl_xor_sync(0xFFFFFFFFu, sum0, 2);
    sum1 += __shfl_xor_sync(0xFFFFFFFFu, sum1, 1);
    sum1 += __shfl_xor_sync(0xFFFFFFFFu, sum1, 2);
    float inv0 = 1.f / sum0, inv1 = 1.f / sum1;

    // D-frag -> fp16 A-frag (hi only; dropped wL term ~2.8e-4 rel)
    uint32_t aW[2][4];
    #pragma unroll
    for (int c = 0; c < 2; c++) {
        #pragma unroll
        for (int h = 0; h < 2; h++) {
            int nt = 2 * c + h;
            aW[c][2 * h + 0] = pack_h(w[nt][0] * inv0, w[nt][1] * inv0);
            aW[c][2 * h + 1] = pack_h(w[nt][2] * inv1, w[nt][3] * inv1);
        }
    }

    // ---- GEMM2: out[16a, 512d] = W[16,32] * V[32,512], fp16 2-pass ----
    const uint4* v2 = g_VF2 + (size_t)b * 4096 + lane;
    float* o0 = out + ((size_t)arow * B_DIM + b) * D_DIM;
    float* o1 = o0 + (size_t)8 * B_DIM * D_DIM;

    uint4 hbuf = v2[0], lbuf = v2[32];
    #pragma unroll 4
    for (int nt = 0; nt < 64; nt++) {
        uint4 nh = v2[(nt + 1) * 64];          // padded: nt==63 safe
        uint4 nl = v2[(nt + 1) * 64 + 32];
        float d0 = 0.f, d1 = 0.f, d2 = 0.f, d3 = 0.f;
        mma_f16(d0, d1, d2, d3, aW[0][0], aW[0][1], aW[0][2], aW[0][3], hbuf.x, hbuf.y);
        mma_f16(d0, d1, d2, d3, aW[1][0], aW[1][1], aW[1][2], aW[1][3], hbuf.z, hbuf.w);
        mma_f16(d0, d1, d2, d3, aW[0][0], aW[0][1], aW[0][2], aW[0][3], lbuf.x, lbuf.y);
        mma_f16(d0, d1, d2, d3, aW[1][0], aW[1][1], aW[1][2], aW[1][3], lbuf.z, lbuf.w);
        int dcol = nt * 8 + (lane & 3) * 2;
        *reinterpret_cast<float2*>(o0 + dcol) = make_float2(d0, d1);
        *reinterpret_cast<float2*>(o1 + dcol) = make_float2(d2, d3);
        hbuf = nh; lbuf = nl;
    }
}

extern "C" void kernel_launch(void* const* d_in, const int* in_sizes, int n_in,
                              void* d_out, int out_size) {
    const float* text = (const float*)d_in[0];
    const float* video = (const float*)d_in[1];
    float* out = (float*)d_out;

    cudaFuncSetAttribute(prep_video, cudaFuncAttributeMaxDynamicSharedMemorySize, 65536);

    prep_text<<<256, 256>>>(text);                 // 65536 entries
    prep_video<<<B_DIM, 256, 65536>>>(video);
    dim3 grid(A_DIM / 128, B_DIM, 1);              // (4, 512)
    abspool_main<<<grid, THREADS>>>(out);
}